// round 1
// baseline (speedup 1.0000x reference)
#include <cuda_runtime.h>
#include <math.h>

#define Bsz   8
#define Lseq  8192
#define Hdim  1024
#define NS    64
#define NTAP  96
#define M_TOT (Bsz * Lseq)   // 65536

// ---------------- scratch (device globals; no allocation allowed) ----------------
__device__ float g_u[(size_t)M_TOT * NS];      // 16 MB  u[b,l,n] = input @ P_in
__device__ float g_conv[(size_t)M_TOT * NS];   // 16 MB  Re(s_{l+1})
__device__ float g_kre[NTAP * NS];
__device__ float g_kim[NTAP * NS];

// ---------------- taps: a_n^d, d = 0..NTAP-1 ----------------
__global__ void taps_kernel(const float* __restrict__ freq, const float* __restrict__ dec) {
    int n = threadIdx.x;
    if (n >= NS) return;
    double rho = -exp((double)dec[n]);   // Re(lam)
    double th  = (double)freq[n];        // Im(lam)
    for (int d = 0; d < NTAP; ++d) {
        double mag = exp(rho * (double)d);
        double ph  = th * (double)d;
        g_kre[d * NS + n] = (float)(mag * cos(ph));
        g_kim[d * NS + n] = (float)(mag * sin(ph));
    }
}

// ---------------- GEMM A: g_u[M,64] = input[M,1024] @ P_in[1024,64] ----------------
#define A_BM 128
#define A_BK 16
__global__ void __launch_bounds__(128) gemmA_kernel(const float* __restrict__ A,
                                                    const float* __restrict__ Bm) {
    __shared__ float As[A_BK][A_BM];   // [k][m]
    __shared__ float Bs[A_BK][NS];     // [k][n]
    int tid = threadIdx.x;
    int m0  = blockIdx.x * A_BM;
    int tm  = tid >> 3;   // 0..15
    int tn  = tid & 7;    // 0..7

    float acc[8][8];
#pragma unroll
    for (int i = 0; i < 8; i++)
#pragma unroll
        for (int j = 0; j < 8; j++) acc[i][j] = 0.f;

    for (int k0 = 0; k0 < Hdim; k0 += A_BK) {
        // A tile: 128 rows x 16 k  (512 float4, 4 per thread, coalesced)
#pragma unroll
        for (int t = 0; t < 4; ++t) {
            int idx = t * 128 + tid;        // 0..511
            int row = idx >> 2;             // 4 float4 per row
            int kq  = (idx & 3) * 4;
            float4 v = *(const float4*)&A[(size_t)(m0 + row) * Hdim + k0 + kq];
            As[kq + 0][row] = v.x; As[kq + 1][row] = v.y;
            As[kq + 2][row] = v.z; As[kq + 3][row] = v.w;
        }
        // B tile: 16 x 64 (256 float4, 2 per thread)
#pragma unroll
        for (int t = 0; t < 2; ++t) {
            int idx = t * 128 + tid;        // 0..255
            int row = idx >> 4;             // 16 float4 per row
            int nq  = (idx & 15) * 4;
            *(float4*)&Bs[row][nq] = *(const float4*)&Bm[(size_t)(k0 + row) * NS + nq];
        }
        __syncthreads();
#pragma unroll
        for (int k = 0; k < A_BK; ++k) {
            float a[8], b[8];
            *(float4*)&a[0] = *(float4*)&As[k][tm * 8];
            *(float4*)&a[4] = *(float4*)&As[k][tm * 8 + 4];
            *(float4*)&b[0] = *(float4*)&Bs[k][tn * 8];
            *(float4*)&b[4] = *(float4*)&Bs[k][tn * 8 + 4];
#pragma unroll
            for (int i = 0; i < 8; i++)
#pragma unroll
                for (int j = 0; j < 8; j++) acc[i][j] += a[i] * b[j];
        }
        __syncthreads();
    }
#pragma unroll
    for (int i = 0; i < 8; i++) {
        int m = m0 + tm * 8 + i;
#pragma unroll
        for (int j = 0; j < 8; j += 4) {
            float4 v = make_float4(acc[i][j], acc[i][j + 1], acc[i][j + 2], acc[i][j + 3]);
            *(float4*)&g_u[(size_t)m * NS + tn * 8 + j] = v;
        }
    }
}

// ---------------- FIR: conv_re[b,l,n] = sum_d kre[d,n] * u_ext[b, l+1-d, n] ----------------
// u_ext[0] = initial_state, u_ext[i] = g_u[i-1] (i>=1), zero for i<0.
#define TL  64
#define WIN (TL + NTAP)   // 160 rows -> 40 KB smem
__global__ void __launch_bounds__(256) fir_kernel(const float* __restrict__ init_state) {
    __shared__ float us[WIN * NS];
    int b    = blockIdx.x >> 7;       // 128 l-blocks per batch
    int lblk = blockIdx.x & 127;
    int l0   = lblk * TL;
    int j0   = l0 + 1;
    int base_i = j0 - (NTAP - 1);     // u_ext index at smem row 0
    int tid  = threadIdx.x;

    for (int idx = tid; idx < WIN * NS; idx += 256) {
        int row = idx >> 6;
        int n   = idx & 63;
        int i   = base_i + row;
        float v;
        if (i < 0)        v = 0.f;
        else if (i == 0)  v = init_state[b * NS + n];
        else              v = g_u[((size_t)b * Lseq + (i - 1)) * NS + n];
        us[idx] = v;
    }
    __syncthreads();

    int n  = tid & 63;
    int lt = tid >> 6;  // 0..3
#pragma unroll
    for (int g = 0; g < 2; ++g) {
        int lb  = lt * 16 + g * 8;      // local l base
        int off = lb + NTAP - 1;        // smem row for (r=0, d=0)
        float acc[8];
#pragma unroll
        for (int r = 0; r < 8; r++) acc[r] = 0.f;

#pragma unroll
        for (int dc = 0; dc < NTAP; dc += 8) {
            float kk[8];
#pragma unroll
            for (int t = 0; t < 8; t++) kk[t] = g_kre[(dc + t) * NS + n];
            float uu[15];
#pragma unroll
            for (int t = 0; t < 15; t++) uu[t] = us[(off - dc - 7 + t) * NS + n];
#pragma unroll
            for (int d = 0; d < 8; ++d)
#pragma unroll
                for (int r = 0; r < 8; r++) acc[r] += kk[d] * uu[7 + r - d];
        }
#pragma unroll
        for (int r = 0; r < 8; r++) {
            int l = l0 + lb + r;
            g_conv[((size_t)b * Lseq + l) * NS + n] = acc[r];
        }
    }
}

// ---------------- final state: s_L (complex), written to the tail of d_out ----------------
__global__ void fstate_kernel(float* __restrict__ outp, int interleaved) {
    int b = blockIdx.x;
    int n = threadIdx.x;
    float re = 0.f, im = 0.f;
#pragma unroll 4
    for (int d = 0; d < NTAP; ++d) {
        // u_ext[L - d] = g_u[L-1-d]  (L-d >= 1 always for d < NTAP)
        float u = g_u[((size_t)b * Lseq + (Lseq - 1 - d)) * NS + n];
        re += g_kre[d * NS + n] * u;
        im += g_kim[d * NS + n] * u;
    }
    float* base = outp + (size_t)M_TOT * Hdim;
    if (interleaved) {
        base[((size_t)b * NS + n) * 2 + 0] = re;
        base[((size_t)b * NS + n) * 2 + 1] = im;
    } else {
        base[(size_t)b * NS + n] = re;
    }
}

// ---------------- GEMM B: out[M,1024] = g_conv[M,64] @ P_out[64,1024] ----------------
#define B_BM 64
#define B_BN 128
#define B_BK 32
__global__ void __launch_bounds__(128) gemmB_kernel(const float* __restrict__ Bm,
                                                    float* __restrict__ C) {
    __shared__ float As[B_BK][B_BM];    // [k][m] 8 KB
    __shared__ float Bs[B_BK][B_BN];    // [k][n] 16 KB
    int tid = threadIdx.x;
    int n0  = blockIdx.x * B_BN;
    int m0  = blockIdx.y * B_BM;
    int tm  = tid >> 4;   // 0..7
    int tn  = tid & 15;   // 0..15

    float acc[8][8];
#pragma unroll
    for (int i = 0; i < 8; i++)
#pragma unroll
        for (int j = 0; j < 8; j++) acc[i][j] = 0.f;

    for (int kc = 0; kc < NS; kc += B_BK) {
        // A tile: 64 rows x 32 k (512 float4, 4 per thread)
#pragma unroll
        for (int t = 0; t < 4; ++t) {
            int idx = t * 128 + tid;
            int row = idx >> 3;             // 8 float4 per row
            int kq  = (idx & 7) * 4;
            float4 v = *(const float4*)&g_conv[(size_t)(m0 + row) * NS + kc + kq];
            As[kq + 0][row] = v.x; As[kq + 1][row] = v.y;
            As[kq + 2][row] = v.z; As[kq + 3][row] = v.w;
        }
        // B tile: 32 rows x 128 n (1024 float4, 8 per thread)
#pragma unroll
        for (int t = 0; t < 8; ++t) {
            int idx = t * 128 + tid;
            int row = idx >> 5;             // 32 float4 per row
            int nq  = (idx & 31) * 4;
            *(float4*)&Bs[row][nq] =
                *(const float4*)&Bm[(size_t)(kc + row) * Hdim + n0 + nq];
        }
        __syncthreads();
#pragma unroll
        for (int k = 0; k < B_BK; ++k) {
            float a[8], b[8];
            *(float4*)&a[0] = *(float4*)&As[k][tm * 8];
            *(float4*)&a[4] = *(float4*)&As[k][tm * 8 + 4];
            *(float4*)&b[0] = *(float4*)&Bs[k][tn * 8];
            *(float4*)&b[4] = *(float4*)&Bs[k][tn * 8 + 4];
#pragma unroll
            for (int i = 0; i < 8; i++)
#pragma unroll
                for (int j = 0; j < 8; j++) acc[i][j] += a[i] * b[j];
        }
        __syncthreads();
    }
#pragma unroll
    for (int i = 0; i < 8; i++) {
        int m = m0 + tm * 8 + i;
#pragma unroll
        for (int j = 0; j < 8; j += 4) {
            float4 v = make_float4(acc[i][j], acc[i][j + 1], acc[i][j + 2], acc[i][j + 3]);
            *(float4*)&C[(size_t)m * Hdim + n0 + tn * 8 + j] = v;
        }
    }
}

// ---------------- launch ----------------
extern "C" void kernel_launch(void* const* d_in, const int* in_sizes, int n_in,
                              void* d_out, int out_size) {
    const float* input = (const float*)d_in[0];   // (B, L, H)
    const float* init  = (const float*)d_in[1];   // (B, NS)
    const float* pin   = (const float*)d_in[2];   // (H, NS)
    const float* pout  = (const float*)d_in[3];   // (NS, H)
    const float* freq  = (const float*)d_in[4];   // (NS)
    const float* dec   = (const float*)d_in[5];   // (NS)
    float* out = (float*)d_out;

    taps_kernel<<<1, 64>>>(freq, dec);
    gemmA_kernel<<<M_TOT / A_BM, 128>>>(input, pin);
    fir_kernel<<<Bsz * (Lseq / TL), 256>>>(init);

    // final state tail: complex64 flattened as float32 pairs (guarded on out_size)
    long long tail = (long long)out_size - (long long)M_TOT * Hdim;
    if (tail >= (long long)Bsz * NS * 2)      fstate_kernel<<<Bsz, NS>>>(out, 1);
    else if (tail >= (long long)Bsz * NS)     fstate_kernel<<<Bsz, NS>>>(out, 0);

    gemmB_kernel<<<dim3(Hdim / B_BN, M_TOT / B_BM), 128>>>(pout, out);
}

// round 4
// speedup vs baseline: 2.0989x; 2.0989x over previous
#include <cuda_runtime.h>
#include <cuda_bf16.h>
#include <math.h>
#include <stdint.h>

#define Bsz   8
#define Lseq  8192
#define Hdim  1024
#define NS    64
#define NTAP  96
#define M_TOT (Bsz * Lseq)   // 65536

// ---------------- scratch ----------------
__device__ float g_u[(size_t)M_TOT * NS];      // 16 MB
__device__ float g_conv[(size_t)M_TOT * NS];   // 16 MB
__device__ float g_kre[NTAP * NS];
__device__ float g_kim[NTAP * NS];

__device__ __forceinline__ uint32_t pack2(__nv_bfloat16 a, __nv_bfloat16 b) {
    return (uint32_t)__bfloat16_as_ushort(a) | ((uint32_t)__bfloat16_as_ushort(b) << 16);
}

// hi/lo split of fp32 -> two bf16
__device__ __forceinline__ void split2(float x, __nv_bfloat16& h, __nv_bfloat16& l) {
    h = __float2bfloat16(x);
    l = __float2bfloat16(x - __bfloat162float(h));
}

// mma.sync m16n8k16 row.col f32.bf16.bf16.f32 (sm_80+ feature, legal under compute_103)
__device__ __forceinline__ void mma16816(float* c, const uint32_t* a, const uint32_t* b) {
    asm volatile(
        "mma.sync.aligned.m16n8k16.row.col.f32.bf16.bf16.f32 "
        "{%0,%1,%2,%3}, {%4,%5,%6,%7}, {%8,%9}, {%0,%1,%2,%3};"
        : "+f"(c[0]), "+f"(c[1]), "+f"(c[2]), "+f"(c[3])
        : "r"(a[0]), "r"(a[1]), "r"(a[2]), "r"(a[3]), "r"(b[0]), "r"(b[1]));
}

// ---------------- taps ----------------
__global__ void taps_kernel(const float* __restrict__ freq, const float* __restrict__ dec) {
    int d = blockIdx.x;
    int n = threadIdx.x;
    double rho = -exp((double)dec[n]);
    double th  = (double)freq[n];
    double mag = exp(rho * (double)d);
    double ph  = th * (double)d;
    g_kre[d * NS + n] = (float)(mag * cos(ph));
    g_kim[d * NS + n] = (float)(mag * sin(ph));
}

// Row stride for k-chunk-32 bf16 tiles: 32*2 + 16 pad = 80 bytes (conflict-free LDS.32)
#define RS 80

// ============ GEMM A (HMMA): g_u[M,64] = input[M,1024] @ P_in[1024,64] ============
// smem: Ah[128xRS] Al Bh[64xRS] Bl  -> 10240+10240+5120+5120 = 30720 B (static)
__global__ void __launch_bounds__(256) gemmA_mma(const float* __restrict__ A,
                                                 const float* __restrict__ Pin) {
    __shared__ char sm[30720];
    char* Ah = sm;
    char* Al = sm + 10240;
    char* Bh = sm + 20480;
    char* Bl = sm + 25600;

    int tid = threadIdx.x;
    int m0  = blockIdx.x * 128;
    int w   = tid >> 5, l = tid & 31;
    int wm  = w >> 1, wn = w & 1;          // warp tile: 32m x 32n
    int lr  = l >> 2, lc = l & 3;          // fragment lane decomposition

    float acc[2][4][4];
#pragma unroll
    for (int i = 0; i < 2; i++)
#pragma unroll
        for (int j = 0; j < 4; j++)
#pragma unroll
            for (int q = 0; q < 4; q++) acc[i][j][q] = 0.f;

    for (int c = 0; c < 32; ++c) {
        int k0 = c * 32;
        // stage A: 128 rows x 32 k fp32 -> bf16 hi/lo (1024 float4, 4/thread)
#pragma unroll
        for (int t = 0; t < 4; ++t) {
            int idx = t * 256 + tid;
            int r = idx >> 3, q = idx & 7;
            float4 v = *(const float4*)&A[(size_t)(m0 + r) * Hdim + k0 + q * 4];
            __nv_bfloat16 h0, h1, h2, h3, l0, l1, l2, l3;
            split2(v.x, h0, l0); split2(v.y, h1, l1);
            split2(v.z, h2, l2); split2(v.w, h3, l3);
            *(uint2*)(Ah + r * RS + q * 8) = make_uint2(pack2(h0, h1), pack2(h2, h3));
            *(uint2*)(Al + r * RS + q * 8) = make_uint2(pack2(l0, l1), pack2(l2, l3));
        }
        // stage B transposed: Bs[n][k] from Pin[k0+kk][n]  (2048 floats, 8/thread)
#pragma unroll
        for (int t = 0; t < 8; ++t) {
            int idx = t * 256 + tid;
            int kk = idx >> 6, n = idx & 63;
            float v = Pin[(size_t)(k0 + kk) * NS + n];
            __nv_bfloat16 h, lo;
            split2(v, h, lo);
            *(__nv_bfloat16*)(Bh + n * RS + kk * 2) = h;
            *(__nv_bfloat16*)(Bl + n * RS + kk * 2) = lo;
        }
        __syncthreads();

#pragma unroll
        for (int ks = 0; ks < 2; ++ks) {
            int kb = ks * 32;  // byte offset of k-step within row
            uint32_t ah[2][4], al[2][4];
#pragma unroll
            for (int mt = 0; mt < 2; ++mt) {
                int r0 = wm * 32 + mt * 16 + lr;
                int co = kb + lc * 4;
                ah[mt][0] = *(const uint32_t*)(Ah + r0 * RS + co);
                ah[mt][1] = *(const uint32_t*)(Ah + (r0 + 8) * RS + co);
                ah[mt][2] = *(const uint32_t*)(Ah + r0 * RS + co + 16);
                ah[mt][3] = *(const uint32_t*)(Ah + (r0 + 8) * RS + co + 16);
                al[mt][0] = *(const uint32_t*)(Al + r0 * RS + co);
                al[mt][1] = *(const uint32_t*)(Al + (r0 + 8) * RS + co);
                al[mt][2] = *(const uint32_t*)(Al + r0 * RS + co + 16);
                al[mt][3] = *(const uint32_t*)(Al + (r0 + 8) * RS + co + 16);
            }
#pragma unroll
            for (int nt = 0; nt < 4; ++nt) {
                int n0 = wn * 32 + nt * 8 + lr;
                int co = kb + lc * 4;
                uint32_t bh[2], bl[2];
                bh[0] = *(const uint32_t*)(Bh + n0 * RS + co);
                bh[1] = *(const uint32_t*)(Bh + n0 * RS + co + 16);
                bl[0] = *(const uint32_t*)(Bl + n0 * RS + co);
                bl[1] = *(const uint32_t*)(Bl + n0 * RS + co + 16);
#pragma unroll
                for (int mt = 0; mt < 2; ++mt) {
                    mma16816(acc[mt][nt], ah[mt], bh);
                    mma16816(acc[mt][nt], ah[mt], bl);
                    mma16816(acc[mt][nt], al[mt], bh);
                }
            }
        }
        __syncthreads();
    }
    // epilogue
#pragma unroll
    for (int mt = 0; mt < 2; ++mt) {
        size_t mrow = (size_t)m0 + wm * 32 + mt * 16 + lr;
#pragma unroll
        for (int nt = 0; nt < 4; ++nt) {
            int n = wn * 32 + nt * 8 + lc * 2;
            *(float2*)&g_u[mrow * NS + n]       = make_float2(acc[mt][nt][0], acc[mt][nt][1]);
            *(float2*)&g_u[(mrow + 8) * NS + n] = make_float2(acc[mt][nt][2], acc[mt][nt][3]);
        }
    }
}

// ---------------- FIR (+ folded final-state) ----------------
#define TL  64
#define WIN (TL + NTAP)   // 160 rows
__global__ void __launch_bounds__(256) fir_kernel(const float* __restrict__ init_state,
                                                  float* __restrict__ outp, int mode) {
    __shared__ float us[WIN * NS];
    int b    = blockIdx.x >> 7;
    int lblk = blockIdx.x & 127;
    int l0   = lblk * TL;
    int base_i = (l0 + 1) - (NTAP - 1);
    int tid  = threadIdx.x;

    for (int idx = tid; idx < WIN * NS; idx += 256) {
        int row = idx >> 6;
        int n   = idx & 63;
        int i   = base_i + row;
        float v;
        if (i < 0)        v = 0.f;
        else if (i == 0)  v = init_state[b * NS + n];
        else              v = g_u[((size_t)b * Lseq + (i - 1)) * NS + n];
        us[idx] = v;
    }
    __syncthreads();

    int n  = tid & 63;
    int lt = tid >> 6;
#pragma unroll
    for (int g = 0; g < 2; ++g) {
        int lb  = lt * 16 + g * 8;
        int off = lb + NTAP - 1;
        float acc[8];
#pragma unroll
        for (int r = 0; r < 8; r++) acc[r] = 0.f;
#pragma unroll
        for (int dc = 0; dc < NTAP; dc += 8) {
            float kk[8];
#pragma unroll
            for (int t = 0; t < 8; t++) kk[t] = g_kre[(dc + t) * NS + n];
            float uu[15];
#pragma unroll
            for (int t = 0; t < 15; t++) uu[t] = us[(off - dc - 7 + t) * NS + n];
#pragma unroll
            for (int d = 0; d < 8; ++d)
#pragma unroll
                for (int r = 0; r < 8; r++) acc[r] += kk[d] * uu[7 + r - d];
        }
#pragma unroll
        for (int r = 0; r < 8; r++)
            g_conv[((size_t)b * Lseq + l0 + lb + r) * NS + n] = acc[r];
    }

    // folded final state s_L (complex) -> tail of d_out
    if (lblk == 127 && mode != 0 && tid < 64) {
        float re = 0.f, im = 0.f;
#pragma unroll 4
        for (int d = 0; d < NTAP; ++d) {
            float u = us[(Lseq - d - base_i) * NS + tid];
            re += g_kre[d * NS + tid] * u;
            im += g_kim[d * NS + tid] * u;
        }
        float* base = outp + (size_t)M_TOT * Hdim;
        if (mode == 2) {
            base[((size_t)b * NS + tid) * 2 + 0] = re;
            base[((size_t)b * NS + tid) * 2 + 1] = im;
        } else {
            base[(size_t)b * NS + tid] = re;
        }
    }
}

// ============ GEMM B (HMMA): out[M,1024] = g_conv[M,64] @ P_out[64,1024] ============
// CTA tile 128m x 128n, K chunks of 32 (x2). smem: Ah Al [128xRS], Bh Bl [128xRS] = 40960 B
__global__ void __launch_bounds__(256) gemmB_mma(const float* __restrict__ Pout,
                                                 float* __restrict__ C) {
    __shared__ char sm[40960];
    char* Ah = sm;
    char* Al = sm + 10240;
    char* Bh = sm + 20480;
    char* Bl = sm + 30720;

    int tid = threadIdx.x;
    int n0c = blockIdx.x * 128;
    int m0  = blockIdx.y * 128;
    int w   = tid >> 5, l = tid & 31;
    int wm  = w >> 1, wn = w & 1;          // warp tile: 32m x 64n
    int lr  = l >> 2, lc = l & 3;

    float acc[2][8][4];
#pragma unroll
    for (int i = 0; i < 2; i++)
#pragma unroll
        for (int j = 0; j < 8; j++)
#pragma unroll
            for (int q = 0; q < 4; q++) acc[i][j][q] = 0.f;

    for (int c = 0; c < 2; ++c) {
        int kc = c * 32;
        // stage A: g_conv tile 128 x 32 (1024 float4, 4/thread)
#pragma unroll
        for (int t = 0; t < 4; ++t) {
            int idx = t * 256 + tid;
            int r = idx >> 3, q = idx & 7;
            float4 v = *(const float4*)&g_conv[(size_t)(m0 + r) * NS + kc + q * 4];
            __nv_bfloat16 h0, h1, h2, h3, l0, l1, l2, l3;
            split2(v.x, h0, l0); split2(v.y, h1, l1);
            split2(v.z, h2, l2); split2(v.w, h3, l3);
            *(uint2*)(Ah + r * RS + q * 8) = make_uint2(pack2(h0, h1), pack2(h2, h3));
            *(uint2*)(Al + r * RS + q * 8) = make_uint2(pack2(l0, l1), pack2(l2, l3));
        }
        // stage B transposed: Bs[n][k] from Pout[kc+kk][n0c+n] (4096 floats, 16/thread)
#pragma unroll
        for (int t = 0; t < 16; ++t) {
            int idx = t * 256 + tid;
            int kk = idx >> 7, n = idx & 127;
            float v = Pout[(size_t)(kc + kk) * Hdim + n0c + n];
            __nv_bfloat16 h, lo;
            split2(v, h, lo);
            *(__nv_bfloat16*)(Bh + n * RS + kk * 2) = h;
            *(__nv_bfloat16*)(Bl + n * RS + kk * 2) = lo;
        }
        __syncthreads();

#pragma unroll
        for (int ks = 0; ks < 2; ++ks) {
            int kb = ks * 32;
            uint32_t ah[2][4], al[2][4];
#pragma unroll
            for (int mt = 0; mt < 2; ++mt) {
                int r0 = wm * 32 + mt * 16 + lr;
                int co = kb + lc * 4;
                ah[mt][0] = *(const uint32_t*)(Ah + r0 * RS + co);
                ah[mt][1] = *(const uint32_t*)(Ah + (r0 + 8) * RS + co);
                ah[mt][2] = *(const uint32_t*)(Ah + r0 * RS + co + 16);
                ah[mt][3] = *(const uint32_t*)(Ah + (r0 + 8) * RS + co + 16);
                al[mt][0] = *(const uint32_t*)(Al + r0 * RS + co);
                al[mt][1] = *(const uint32_t*)(Al + (r0 + 8) * RS + co);
                al[mt][2] = *(const uint32_t*)(Al + r0 * RS + co + 16);
                al[mt][3] = *(const uint32_t*)(Al + (r0 + 8) * RS + co + 16);
            }
#pragma unroll
            for (int nt = 0; nt < 8; ++nt) {
                int n0 = wn * 64 + nt * 8 + lr;
                int co = kb + lc * 4;
                uint32_t bh[2], bl[2];
                bh[0] = *(const uint32_t*)(Bh + n0 * RS + co);
                bh[1] = *(const uint32_t*)(Bh + n0 * RS + co + 16);
                bl[0] = *(const uint32_t*)(Bl + n0 * RS + co);
                bl[1] = *(const uint32_t*)(Bl + n0 * RS + co + 16);
#pragma unroll
                for (int mt = 0; mt < 2; ++mt) {
                    mma16816(acc[mt][nt], ah[mt], bh);
                    mma16816(acc[mt][nt], ah[mt], bl);
                    mma16816(acc[mt][nt], al[mt], bh);
                }
            }
        }
        __syncthreads();
    }
    // epilogue: direct float2 stores
#pragma unroll
    for (int mt = 0; mt < 2; ++mt) {
        size_t mrow = (size_t)m0 + wm * 32 + mt * 16 + lr;
#pragma unroll
        for (int nt = 0; nt < 8; ++nt) {
            int n = n0c + wn * 64 + nt * 8 + lc * 2;
            *(float2*)&C[mrow * Hdim + n]       = make_float2(acc[mt][nt][0], acc[mt][nt][1]);
            *(float2*)&C[(mrow + 8) * Hdim + n] = make_float2(acc[mt][nt][2], acc[mt][nt][3]);
        }
    }
}

// ---------------- launch ----------------
extern "C" void kernel_launch(void* const* d_in, const int* in_sizes, int n_in,
                              void* d_out, int out_size) {
    const float* input = (const float*)d_in[0];
    const float* init  = (const float*)d_in[1];
    const float* pin   = (const float*)d_in[2];
    const float* pout  = (const float*)d_in[3];
    const float* freq  = (const float*)d_in[4];
    const float* dec   = (const float*)d_in[5];
    float* out = (float*)d_out;

    long long tail = (long long)out_size - (long long)M_TOT * Hdim;
    int mode = 0;
    if (tail >= (long long)Bsz * NS * 2)  mode = 2;
    else if (tail >= (long long)Bsz * NS) mode = 1;

    taps_kernel<<<NTAP, NS>>>(freq, dec);
    gemmA_mma<<<M_TOT / 128, 256>>>(input, pin);
    fir_kernel<<<Bsz * (Lseq / TL), 256>>>(init, out, mode);
    gemmB_mma<<<dim3(Hdim / 128, M_TOT / 128), 256>>>(pout, out);
}

// round 6
// speedup vs baseline: 2.6310x; 1.2535x over previous
#include <cuda_runtime.h>
#include <cuda_bf16.h>
#include <math.h>
#include <stdint.h>

#define Bsz   8
#define Lseq  8192
#define Hdim  1024
#define NS    64
#define NTAP  48
#define M_TOT (Bsz * Lseq)   // 65536

typedef unsigned short ushort_t;

// ---------------- scratch ----------------
__device__ float    g_u[(size_t)M_TOT * NS];        // 16 MB
__device__ ushort_t g_ch[(size_t)M_TOT * NS];       // 8 MB  conv hi (bf16 bits)
__device__ ushort_t g_cl[(size_t)M_TOT * NS];       // 8 MB  conv lo
__device__ ushort_t g_pinH[NS * Hdim], g_pinL[NS * Hdim];       // [n][k] 128KB ea
__device__ ushort_t g_poutH[Hdim * NS], g_poutL[Hdim * NS];     // [n][k] 128KB ea
__device__ float g_kre[NTAP * NS];
__device__ float g_kim[NTAP * NS];

__device__ __forceinline__ uint32_t pack2(__nv_bfloat16 a, __nv_bfloat16 b) {
    return (uint32_t)__bfloat16_as_ushort(a) | ((uint32_t)__bfloat16_as_ushort(b) << 16);
}
__device__ __forceinline__ void split2(float x, __nv_bfloat16& h, __nv_bfloat16& l) {
    h = __float2bfloat16(x);
    l = __float2bfloat16(x - __bfloat162float(h));
}
__device__ __forceinline__ void mma16816(float* c, const uint32_t* a, const uint32_t* b) {
    asm volatile(
        "mma.sync.aligned.m16n8k16.row.col.f32.bf16.bf16.f32 "
        "{%0,%1,%2,%3}, {%4,%5,%6,%7}, {%8,%9}, {%0,%1,%2,%3};"
        : "+f"(c[0]), "+f"(c[1]), "+f"(c[2]), "+f"(c[3])
        : "r"(a[0]), "r"(a[1]), "r"(a[2]), "r"(a[3]), "r"(b[0]), "r"(b[1]));
}

// ---------------- taps ----------------
__global__ void taps_kernel(const float* __restrict__ freq, const float* __restrict__ dec) {
    int d = blockIdx.x;
    int n = threadIdx.x;
    double rho = -exp((double)dec[n]);
    double th  = (double)freq[n];
    double mag = exp(rho * (double)d);
    double ph  = th * (double)d;
    g_kre[d * NS + n] = (float)(mag * cos(ph));
    g_kim[d * NS + n] = (float)(mag * sin(ph));
}

// ---------------- projection planes: bf16 hi/lo, [n][k] (transposed) ----------------
__global__ void __launch_bounds__(256) prep_planes(const float* __restrict__ pin,
                                                   const float* __restrict__ pout) {
    int idx = blockIdx.x * 256 + threadIdx.x;   // 0..131071
    __nv_bfloat16 h, l;
    if (idx < NS * Hdim) {                      // pin plane: [n<64][k<1024]
        int n = idx >> 10, k = idx & 1023;
        split2(pin[(size_t)k * NS + n], h, l);
        g_pinH[idx] = __bfloat16_as_ushort(h);
        g_pinL[idx] = __bfloat16_as_ushort(l);
    } else {                                    // pout plane: [n<1024][k<64]
        int j = idx - NS * Hdim;
        int n = j >> 6, k = j & 63;
        split2(pout[(size_t)k * Hdim + n], h, l);
        g_poutH[j] = __bfloat16_as_ushort(h);
        g_poutL[j] = __bfloat16_as_ushort(l);
    }
}

// Row stride for 32-k bf16 tiles: 64B data + 16B pad
#define RS 80

// ============ GEMM A (HMMA, pipelined): g_u[M,64] = input[M,1024] @ P_in[1024,64] ============
__global__ void __launch_bounds__(256) gemmA_mma(const float* __restrict__ A) {
    __shared__ char sm[30720];
    char* Ah = sm;
    char* Al = sm + 10240;
    char* Bh = sm + 20480;
    char* Bl = sm + 25600;

    int tid = threadIdx.x;
    int m0  = blockIdx.x * 128;
    int w   = tid >> 5, l = tid & 31;
    int wm  = w >> 1, wn = w & 1;          // warp tile 32m x 32n
    int lr  = l >> 2, lc = l & 3;

    // staging geometry (fixed per thread)
    int ra[4], qa[4];
#pragma unroll
    for (int t = 0; t < 4; ++t) { int idx = t * 256 + tid; ra[t] = idx >> 3; qa[t] = idx & 7; }
    int rB = tid >> 2, qB = tid & 3;

    float acc[2][4][4];
#pragma unroll
    for (int i = 0; i < 2; i++)
#pragma unroll
        for (int j = 0; j < 4; j++)
#pragma unroll
            for (int q = 0; q < 4; q++) acc[i][j][q] = 0.f;

    // prologue: prefetch chunk 0
    float4 areg[4];
    uint4 bhreg, blreg;
#pragma unroll
    for (int t = 0; t < 4; ++t)
        areg[t] = *(const float4*)&A[(size_t)(m0 + ra[t]) * Hdim + qa[t] * 4];
    bhreg = *(const uint4*)&g_pinH[rB * Hdim + qB * 8];
    blreg = *(const uint4*)&g_pinL[rB * Hdim + qB * 8];

    for (int c = 0; c < 32; ++c) {
        // STS current chunk from regs
#pragma unroll
        for (int t = 0; t < 4; ++t) {
            __nv_bfloat16 h0, h1, h2, h3, l0, l1, l2, l3;
            split2(areg[t].x, h0, l0); split2(areg[t].y, h1, l1);
            split2(areg[t].z, h2, l2); split2(areg[t].w, h3, l3);
            *(uint2*)(Ah + ra[t] * RS + qa[t] * 8) = make_uint2(pack2(h0, h1), pack2(h2, h3));
            *(uint2*)(Al + ra[t] * RS + qa[t] * 8) = make_uint2(pack2(l0, l1), pack2(l2, l3));
        }
        *(uint4*)(Bh + rB * RS + qB * 16) = bhreg;
        *(uint4*)(Bl + rB * RS + qB * 16) = blreg;
        __syncthreads();

        // prefetch next chunk (overlaps with MMA below)
        if (c < 31) {
            int k1 = (c + 1) * 32;
#pragma unroll
            for (int t = 0; t < 4; ++t)
                areg[t] = *(const float4*)&A[(size_t)(m0 + ra[t]) * Hdim + k1 + qa[t] * 4];
            bhreg = *(const uint4*)&g_pinH[rB * Hdim + k1 + qB * 8];
            blreg = *(const uint4*)&g_pinL[rB * Hdim + k1 + qB * 8];
        }

#pragma unroll
        for (int ks = 0; ks < 2; ++ks) {
            int kb = ks * 32;
            uint32_t ah[2][4], al[2][4];
#pragma unroll
            for (int mt = 0; mt < 2; ++mt) {
                int r0 = wm * 32 + mt * 16 + lr;
                int co = kb + lc * 4;
                ah[mt][0] = *(const uint32_t*)(Ah + r0 * RS + co);
                ah[mt][1] = *(const uint32_t*)(Ah + (r0 + 8) * RS + co);
                ah[mt][2] = *(const uint32_t*)(Ah + r0 * RS + co + 16);
                ah[mt][3] = *(const uint32_t*)(Ah + (r0 + 8) * RS + co + 16);
                al[mt][0] = *(const uint32_t*)(Al + r0 * RS + co);
                al[mt][1] = *(const uint32_t*)(Al + (r0 + 8) * RS + co);
                al[mt][2] = *(const uint32_t*)(Al + r0 * RS + co + 16);
                al[mt][3] = *(const uint32_t*)(Al + (r0 + 8) * RS + co + 16);
            }
#pragma unroll
            for (int nt = 0; nt < 4; ++nt) {
                int n0 = wn * 32 + nt * 8 + lr;
                int co = kb + lc * 4;
                uint32_t bh[2], bl[2];
                bh[0] = *(const uint32_t*)(Bh + n0 * RS + co);
                bh[1] = *(const uint32_t*)(Bh + n0 * RS + co + 16);
                bl[0] = *(const uint32_t*)(Bl + n0 * RS + co);
                bl[1] = *(const uint32_t*)(Bl + n0 * RS + co + 16);
#pragma unroll
                for (int mt = 0; mt < 2; ++mt) {
                    mma16816(acc[mt][nt], ah[mt], bh);
                    mma16816(acc[mt][nt], ah[mt], bl);
                    mma16816(acc[mt][nt], al[mt], bh);
                }
            }
        }
        __syncthreads();
    }
#pragma unroll
    for (int mt = 0; mt < 2; ++mt) {
        size_t mrow = (size_t)m0 + wm * 32 + mt * 16 + lr;
#pragma unroll
        for (int nt = 0; nt < 4; ++nt) {
            int n = wn * 32 + nt * 8 + lc * 2;
            *(float2*)&g_u[mrow * NS + n]       = make_float2(acc[mt][nt][0], acc[mt][nt][1]);
            *(float2*)&g_u[(mrow + 8) * NS + n] = make_float2(acc[mt][nt][2], acc[mt][nt][3]);
        }
    }
}

// ---------------- FIR (NTAP=48) -> bf16 hi/lo planes; folded final-state ----------------
#define TL  64
#define WIN (TL + NTAP)   // 112 rows
__global__ void __launch_bounds__(256) fir_kernel(const float* __restrict__ init_state,
                                                  float* __restrict__ outp, int mode) {
    __shared__ float us[WIN * NS];
    int b    = blockIdx.x >> 7;
    int lblk = blockIdx.x & 127;
    int l0   = lblk * TL;
    int base_i = (l0 + 1) - (NTAP - 1);
    int tid  = threadIdx.x;

    for (int idx = tid; idx < WIN * NS; idx += 256) {
        int row = idx >> 6;
        int n   = idx & 63;
        int i   = base_i + row;
        float v;
        if (i < 0)        v = 0.f;
        else if (i == 0)  v = init_state[b * NS + n];
        else              v = g_u[((size_t)b * Lseq + (i - 1)) * NS + n];
        us[idx] = v;
    }
    __syncthreads();

    int n  = tid & 63;
    int lt = tid >> 6;
#pragma unroll
    for (int g = 0; g < 2; ++g) {
        int lb  = lt * 16 + g * 8;
        int off = lb + NTAP - 1;
        float acc[8];
#pragma unroll
        for (int r = 0; r < 8; r++) acc[r] = 0.f;
#pragma unroll
        for (int dc = 0; dc < NTAP; dc += 8) {
            float kk[8];
#pragma unroll
            for (int t = 0; t < 8; t++) kk[t] = g_kre[(dc + t) * NS + n];
            float uu[15];
#pragma unroll
            for (int t = 0; t < 15; t++) uu[t] = us[(off - dc - 7 + t) * NS + n];
#pragma unroll
            for (int d = 0; d < 8; ++d)
#pragma unroll
                for (int r = 0; r < 8; r++) acc[r] += kk[d] * uu[7 + r - d];
        }
#pragma unroll
        for (int r = 0; r < 8; r++) {
            size_t o = ((size_t)b * Lseq + l0 + lb + r) * NS + n;
            __nv_bfloat16 h, lo;
            split2(acc[r], h, lo);
            g_ch[o] = __bfloat16_as_ushort(h);
            g_cl[o] = __bfloat16_as_ushort(lo);
        }
    }

    // folded final state s_L (complex) -> tail of d_out
    if (lblk == 127 && mode != 0 && tid < 64) {
        float re = 0.f, im = 0.f;
#pragma unroll 4
        for (int d = 0; d < NTAP; ++d) {
            float u = us[(Lseq - d - base_i) * NS + tid];
            re += g_kre[d * NS + tid] * u;
            im += g_kim[d * NS + tid] * u;
        }
        float* base = outp + (size_t)M_TOT * Hdim;
        if (mode == 2) {
            base[((size_t)b * NS + tid) * 2 + 0] = re;
            base[((size_t)b * NS + tid) * 2 + 1] = im;
        } else {
            base[(size_t)b * NS + tid] = re;
        }
    }
}

// ============ GEMM B (HMMA): out[M,1024] = conv[M,64] @ P_out[64,1024] ============
// All operands pre-converted bf16 planes -> staging is pure uint4 copies.
__global__ void __launch_bounds__(256) gemmB_mma(float* __restrict__ C) {
    __shared__ char sm[40960];
    char* Ah = sm;
    char* Al = sm + 10240;
    char* Bh = sm + 20480;
    char* Bl = sm + 30720;

    int tid = threadIdx.x;
    int n0c = blockIdx.x * 128;
    int m0  = blockIdx.y * 128;
    int w   = tid >> 5, l = tid & 31;
    int wm  = w >> 1, wn = w & 1;          // warp tile 32m x 64n
    int lr  = l >> 2, lc = l & 3;

    float acc[2][8][4];
#pragma unroll
    for (int i = 0; i < 2; i++)
#pragma unroll
        for (int j = 0; j < 8; j++)
#pragma unroll
            for (int q = 0; q < 4; q++) acc[i][j][q] = 0.f;

    for (int c = 0; c < 2; ++c) {
        int kc = c * 32;
        // direct-copy staging: 512 uint4 per plane, 2/thread
#pragma unroll
        for (int t = 0; t < 2; ++t) {
            int idx = t * 256 + tid;
            int r = idx >> 2, q = idx & 3;
            *(uint4*)(Ah + r * RS + q * 16) = *(const uint4*)&g_ch[(size_t)(m0 + r) * NS + kc + q * 8];
            *(uint4*)(Al + r * RS + q * 16) = *(const uint4*)&g_cl[(size_t)(m0 + r) * NS + kc + q * 8];
            *(uint4*)(Bh + r * RS + q * 16) = *(const uint4*)&g_poutH[(size_t)(n0c + r) * NS + kc + q * 8];
            *(uint4*)(Bl + r * RS + q * 16) = *(const uint4*)&g_poutL[(size_t)(n0c + r) * NS + kc + q * 8];
        }
        __syncthreads();

#pragma unroll
        for (int ks = 0; ks < 2; ++ks) {
            int kb = ks * 32;
            uint32_t ah[2][4], al[2][4];
#pragma unroll
            for (int mt = 0; mt < 2; ++mt) {
                int r0 = wm * 32 + mt * 16 + lr;
                int co = kb + lc * 4;
                ah[mt][0] = *(const uint32_t*)(Ah + r0 * RS + co);
                ah[mt][1] = *(const uint32_t*)(Ah + (r0 + 8) * RS + co);
                ah[mt][2] = *(const uint32_t*)(Ah + r0 * RS + co + 16);
                ah[mt][3] = *(const uint32_t*)(Ah + (r0 + 8) * RS + co + 16);
                al[mt][0] = *(const uint32_t*)(Al + r0 * RS + co);
                al[mt][1] = *(const uint32_t*)(Al + (r0 + 8) * RS + co);
                al[mt][2] = *(const uint32_t*)(Al + r0 * RS + co + 16);
                al[mt][3] = *(const uint32_t*)(Al + (r0 + 8) * RS + co + 16);
            }
#pragma unroll
            for (int nt = 0; nt < 8; ++nt) {
                int n0 = wn * 64 + nt * 8 + lr;
                int co = kb + lc * 4;
                uint32_t bh[2], bl[2];
                bh[0] = *(const uint32_t*)(Bh + n0 * RS + co);
                bh[1] = *(const uint32_t*)(Bh + n0 * RS + co + 16);
                bl[0] = *(const uint32_t*)(Bl + n0 * RS + co);
                bl[1] = *(const uint32_t*)(Bl + n0 * RS + co + 16);
#pragma unroll
                for (int mt = 0; mt < 2; ++mt) {
                    mma16816(acc[mt][nt], ah[mt], bh);
                    mma16816(acc[mt][nt], ah[mt], bl);
                    mma16816(acc[mt][nt], al[mt], bh);
                }
            }
        }
        __syncthreads();
    }
#pragma unroll
    for (int mt = 0; mt < 2; ++mt) {
        size_t mrow = (size_t)m0 + wm * 32 + mt * 16 + lr;
#pragma unroll
        for (int nt = 0; nt < 8; ++nt) {
            int n = n0c + wn * 64 + nt * 8 + lc * 2;
            *(float2*)&C[mrow * Hdim + n]       = make_float2(acc[mt][nt][0], acc[mt][nt][1]);
            *(float2*)&C[(mrow + 8) * Hdim + n] = make_float2(acc[mt][nt][2], acc[mt][nt][3]);
        }
    }
}

// ---------------- launch ----------------
extern "C" void kernel_launch(void* const* d_in, const int* in_sizes, int n_in,
                              void* d_out, int out_size) {
    const float* input = (const float*)d_in[0];
    const float* init  = (const float*)d_in[1];
    const float* pin   = (const float*)d_in[2];
    const float* pout  = (const float*)d_in[3];
    const float* freq  = (const float*)d_in[4];
    const float* dec   = (const float*)d_in[5];
    float* out = (float*)d_out;

    long long tail = (long long)out_size - (long long)M_TOT * Hdim;
    int mode = 0;
    if (tail >= (long long)Bsz * NS * 2)  mode = 2;
    else if (tail >= (long long)Bsz * NS) mode = 1;

    taps_kernel<<<NTAP, NS>>>(freq, dec);
    prep_planes<<<512, 256>>>(pin, pout);
    gemmA_mma<<<M_TOT / 128, 256>>>(input);
    fir_kernel<<<Bsz * (Lseq / TL), 256>>>(init, out, mode);
    gemmB_mma<<<dim3(Hdim / 128, M_TOT / 128), 256>>>(out);
}